// round 2
// baseline (speedup 1.0000x reference)
#include <cuda_runtime.h>
#include <math.h>

#define KP      4
#define DMODEL  1024
#define DFF     4096
#define NTOK    2048
#define RANK    16

// ---- device scratch (allocation-free rule: __device__ globals) ----
__device__ float g_W1[(size_t)KP * DMODEL * DFF];   // [k][dm][dff]
__device__ float g_W2[(size_t)KP * DFF * DMODEL];   // [k][dff][dm]
__device__ float g_H [(size_t)KP * NTOK * DFF];     // [k][n][dff]
__device__ float g_gates[NTOK * KP];

// ---------------------------------------------------------------------------
// Build dense W1[k][a*32+b][x*64+y] = sum_r G1[k,a,x,r] * G2[k,r,b,y]
// G1: [K,32,64,16]  G2: [K,16,32,64]
// ---------------------------------------------------------------------------
__global__ void build_w1(const float* __restrict__ G1, const float* __restrict__ G2) {
    int j = blockIdx.x * blockDim.x + threadIdx.x;  // 0..DFF-1
    int i = blockIdx.y;                             // 0..DMODEL-1
    int k = blockIdx.z;
    int a = i >> 5, b = i & 31;
    int x = j >> 6, y = j & 63;
    const float* g1 = G1 + (((size_t)(k * 32 + a) * 64 + x) * 16);
    const float* g2 = G2 + ((size_t)k * 16) * 32 * 64 + (size_t)b * 64 + y;
    float s = 0.f;
#pragma unroll
    for (int r = 0; r < RANK; r++)
        s += g1[r] * g2[(size_t)r * 32 * 64];
    g_W1[((size_t)k * DMODEL + i) * DFF + j] = s;
}

// Build dense W2[k][a*64+b][x*32+y] = sum_r C1[k,a,x,r] * C2[k,r,b,y]
// C1: [K,64,32,16]  C2: [K,16,64,32]
__global__ void build_w2(const float* __restrict__ C1, const float* __restrict__ C2) {
    int j = blockIdx.x * blockDim.x + threadIdx.x;  // 0..DMODEL-1
    int i = blockIdx.y;                             // 0..DFF-1
    int k = blockIdx.z;
    int a = i >> 6, b = i & 63;
    int x = j >> 5, y = j & 31;
    const float* c1 = C1 + (((size_t)(k * 64 + a) * 32 + x) * 16);
    const float* c2 = C2 + ((size_t)k * 16) * 64 * 32 + (size_t)b * 32 + y;
    float s = 0.f;
#pragma unroll
    for (int r = 0; r < RANK; r++)
        s += c1[r] * c2[(size_t)r * 64 * 32];
    g_W2[((size_t)k * DFF + i) * DMODEL + j] = s;
}

// ---------------------------------------------------------------------------
// Routing gates: one warp per token. logits = tokens . path_bases[k]; softmax.
// ---------------------------------------------------------------------------
__global__ void gates_kernel(const float* __restrict__ tokens,
                             const float* __restrict__ pb) {
    int n = blockIdx.x;
    int lane = threadIdx.x;
    float s0 = 0.f, s1 = 0.f, s2 = 0.f, s3 = 0.f;
    const float* t = tokens + (size_t)n * DMODEL;
    for (int i = lane; i < DMODEL; i += 32) {
        float tv = t[i];
        s0 += tv * pb[i];
        s1 += tv * pb[DMODEL + i];
        s2 += tv * pb[2 * DMODEL + i];
        s3 += tv * pb[3 * DMODEL + i];
    }
#pragma unroll
    for (int o = 16; o > 0; o >>= 1) {
        s0 += __shfl_down_sync(0xffffffffu, s0, o);
        s1 += __shfl_down_sync(0xffffffffu, s1, o);
        s2 += __shfl_down_sync(0xffffffffu, s2, o);
        s3 += __shfl_down_sync(0xffffffffu, s3, o);
    }
    if (lane == 0) {
        float m = fmaxf(fmaxf(s0, s1), fmaxf(s2, s3));
        float e0 = expf(s0 - m), e1 = expf(s1 - m), e2 = expf(s2 - m), e3 = expf(s3 - m);
        float inv = 1.f / (e0 + e1 + e2 + e3);
        g_gates[n * KP + 0] = e0 * inv;
        g_gates[n * KP + 1] = e1 * inv;
        g_gates[n * KP + 2] = e2 * inv;
        g_gates[n * KP + 3] = e3 * inv;
    }
}

__device__ __forceinline__ float gelu_tanh(float v) {
    // matches jax.nn.gelu(approximate=True)
    float c = 0.7978845608028654f;
    float t = tanhf(c * (v + 0.044715f * v * v * v));
    return 0.5f * v * (1.0f + t);
}

// ---------------------------------------------------------------------------
// GEMM1: h[k] = gelu(tokens @ W1[k]);  M=2048 N=4096 K=1024, grid.z = path
// 128x128 block tile, k-tile 16, 256 threads, 8x8 per-thread microtile.
// ---------------------------------------------------------------------------
__global__ __launch_bounds__(256, 2) void gemm1(const float* __restrict__ A) {
    int kp = blockIdx.z;
    const float* B = g_W1 + (size_t)kp * DMODEL * DFF;
    float* C = g_H + (size_t)kp * NTOK * DFF;
    const int m0 = blockIdx.y * 128;
    const int n0 = blockIdx.x * 128;

    __shared__ float As[16][132];  // transposed: As[kk][m]
    __shared__ float Bs[16][128];

    int tid = threadIdx.x;
    int tx = tid & 15, ty = tid >> 4;
    float acc[8][8];
#pragma unroll
    for (int i = 0; i < 8; i++)
#pragma unroll
        for (int j = 0; j < 8; j++) acc[i][j] = 0.f;

    for (int kt = 0; kt < DMODEL; kt += 16) {
#pragma unroll
        for (int u = 0; u < 2; u++) {  // A tile: 128 x 16 (512 float4)
            int f = (tid << 1) | u;
            int row = f >> 2, c4 = (f & 3) << 2;
            float4 v = *(const float4*)(A + (size_t)(m0 + row) * DMODEL + kt + c4);
            As[c4 + 0][row] = v.x; As[c4 + 1][row] = v.y;
            As[c4 + 2][row] = v.z; As[c4 + 3][row] = v.w;
        }
#pragma unroll
        for (int u = 0; u < 2; u++) {  // B tile: 16 x 128
            int f = (tid << 1) | u;
            int row = f >> 5, c4 = (f & 31) << 2;
            *(float4*)&Bs[row][c4] =
                *(const float4*)(B + (size_t)(kt + row) * DFF + n0 + c4);
        }
        __syncthreads();
#pragma unroll
        for (int kk = 0; kk < 16; kk++) {
            float a[8], b[8];
            *(float4*)(a)     = *(float4*)&As[kk][ty * 8];
            *(float4*)(a + 4) = *(float4*)&As[kk][ty * 8 + 4];
            *(float4*)(b)     = *(float4*)&Bs[kk][tx * 8];
            *(float4*)(b + 4) = *(float4*)&Bs[kk][tx * 8 + 4];
#pragma unroll
            for (int i = 0; i < 8; i++)
#pragma unroll
                for (int j = 0; j < 8; j++) acc[i][j] = fmaf(a[i], b[j], acc[i][j]);
        }
        __syncthreads();
    }
    // epilogue: gelu + store
#pragma unroll
    for (int i = 0; i < 8; i++) {
        size_t row = m0 + ty * 8 + i;
#pragma unroll
        for (int j4 = 0; j4 < 2; j4++) {
            float4 v;
            v.x = gelu_tanh(acc[i][j4 * 4 + 0]);
            v.y = gelu_tanh(acc[i][j4 * 4 + 1]);
            v.z = gelu_tanh(acc[i][j4 * 4 + 2]);
            v.w = gelu_tanh(acc[i][j4 * 4 + 3]);
            *(float4*)(C + row * DFF + n0 + tx * 8 + j4 * 4) = v;
        }
    }
}

// ---------------------------------------------------------------------------
// GEMM2 + routing: out[n,d] = sum_k gate[n,k]*(1+pw[k,d]) * (h[k,n,:] @ W2[k][:,d])
// gate folded into A tile, (1+pw) folded into B tile -> single accumulator.
// M=2048 N=1024 K=4*4096.
// ---------------------------------------------------------------------------
__global__ __launch_bounds__(256, 2) void gemm2(const float* __restrict__ pw,
                                                float* __restrict__ out) {
    const int m0 = blockIdx.y * 128;
    const int n0 = blockIdx.x * 128;

    __shared__ float As[16][132];
    __shared__ float Bs[16][128];

    int tid = threadIdx.x;
    int tx = tid & 15, ty = tid >> 4;
    float acc[8][8];
#pragma unroll
    for (int i = 0; i < 8; i++)
#pragma unroll
        for (int j = 0; j < 8; j++) acc[i][j] = 0.f;

    for (int kp = 0; kp < KP; kp++) {
        const float* A = g_H + (size_t)kp * NTOK * DFF;
        const float* B = g_W2 + (size_t)kp * DFF * DMODEL;
        for (int kt = 0; kt < DFF; kt += 16) {
#pragma unroll
            for (int u = 0; u < 2; u++) {  // A tile (scaled by gate)
                int f = (tid << 1) | u;
                int row = f >> 2, c4 = (f & 3) << 2;
                float g = g_gates[(m0 + row) * KP + kp];
                float4 v = *(const float4*)(A + (size_t)(m0 + row) * DFF + kt + c4);
                As[c4 + 0][row] = v.x * g; As[c4 + 1][row] = v.y * g;
                As[c4 + 2][row] = v.z * g; As[c4 + 3][row] = v.w * g;
            }
#pragma unroll
            for (int u = 0; u < 2; u++) {  // B tile (scaled by 1+pw)
                int f = (tid << 1) | u;
                int row = f >> 5, c4 = (f & 31) << 2;
                float4 v = *(const float4*)(B + (size_t)(kt + row) * DMODEL + n0 + c4);
                float4 w = *(const float4*)(pw + (size_t)kp * DMODEL + n0 + c4);
                v.x *= (1.f + w.x); v.y *= (1.f + w.y);
                v.z *= (1.f + w.z); v.w *= (1.f + w.w);
                *(float4*)&Bs[row][c4] = v;
            }
            __syncthreads();
#pragma unroll
            for (int kk = 0; kk < 16; kk++) {
                float a[8], b[8];
                *(float4*)(a)     = *(float4*)&As[kk][ty * 8];
                *(float4*)(a + 4) = *(float4*)&As[kk][ty * 8 + 4];
                *(float4*)(b)     = *(float4*)&Bs[kk][tx * 8];
                *(float4*)(b + 4) = *(float4*)&Bs[kk][tx * 8 + 4];
#pragma unroll
                for (int i = 0; i < 8; i++)
#pragma unroll
                    for (int j = 0; j < 8; j++) acc[i][j] = fmaf(a[i], b[j], acc[i][j]);
            }
            __syncthreads();
        }
    }
#pragma unroll
    for (int i = 0; i < 8; i++) {
        size_t row = m0 + ty * 8 + i;
#pragma unroll
        for (int j4 = 0; j4 < 2; j4++)
            *(float4*)(out + row * DMODEL + n0 + tx * 8 + j4 * 4) =
                *(float4*)&acc[i][j4 * 4];
    }
}

// ---------------------------------------------------------------------------
extern "C" void kernel_launch(void* const* d_in, const int* in_sizes, int n_in,
                              void* d_out, int out_size) {
    const float* tokens = (const float*)d_in[0];
    const float* G1     = (const float*)d_in[1];  // ffn1_core1 [4,32,64,16]
    const float* G2     = (const float*)d_in[2];  // ffn1_core2 [4,16,32,64]
    const float* C1     = (const float*)d_in[3];  // ffn2_core1 [4,64,32,16]
    const float* C2     = (const float*)d_in[4];  // ffn2_core2 [4,16,64,32]
    const float* pb     = (const float*)d_in[5];  // path_bases [4,1024]
    const float* pw     = (const float*)d_in[6];  // path_weights [4,1024]
    float* out = (float*)d_out;

    build_w1<<<dim3(DFF / 256, DMODEL, KP), 256>>>(G1, G2);
    build_w2<<<dim3(DMODEL / 256, DFF, KP), 256>>>(C1, C2);
    gates_kernel<<<NTOK, 32>>>(tokens, pb);
    gemm1<<<dim3(DFF / 128, NTOK / 128, KP), 256>>>(tokens);
    gemm2<<<dim3(DMODEL / 128, NTOK / 128), 256>>>(pw, out);
}

// round 3
// speedup vs baseline: 1.0002x; 1.0002x over previous
#include <cuda_runtime.h>
#include <math.h>

#define KP      4
#define DMODEL  1024
#define DFF     4096
#define NTOK    2048
#define RANK    16

// ---- device scratch (allocation-free rule: __device__ globals) ----
__device__ float g_W1[(size_t)KP * DMODEL * DFF];   // [k][dm][dff]
__device__ float g_W2[(size_t)KP * DFF * DMODEL];   // [k][dff][dm]
__device__ float g_H [(size_t)KP * NTOK * DFF];     // [k][n][dff]
__device__ float g_gates[NTOK * KP];

// ---------------------------------------------------------------------------
// Build dense W1[k][a*32+b][x*64+y] = sum_r G1[k,a,x,r] * G2[k,r,b,y]
// G1: [K,32,64,16]  G2: [K,16,32,64]
// ---------------------------------------------------------------------------
__global__ void build_w1(const float* __restrict__ G1, const float* __restrict__ G2) {
    int j = blockIdx.x * blockDim.x + threadIdx.x;  // 0..DFF-1
    int i = blockIdx.y;                             // 0..DMODEL-1
    int k = blockIdx.z;
    int a = i >> 5, b = i & 31;
    int x = j >> 6, y = j & 63;
    const float* g1 = G1 + (((size_t)(k * 32 + a) * 64 + x) * 16);
    const float* g2 = G2 + ((size_t)k * 16) * 32 * 64 + (size_t)b * 64 + y;
    float s = 0.f;
#pragma unroll
    for (int r = 0; r < RANK; r++)
        s += g1[r] * g2[(size_t)r * 32 * 64];
    g_W1[((size_t)k * DMODEL + i) * DFF + j] = s;
}

// Build dense W2[k][a*64+b][x*32+y] = sum_r C1[k,a,x,r] * C2[k,r,b,y]
// C1: [K,64,32,16]  C2: [K,16,64,32]
__global__ void build_w2(const float* __restrict__ C1, const float* __restrict__ C2) {
    int j = blockIdx.x * blockDim.x + threadIdx.x;  // 0..DMODEL-1
    int i = blockIdx.y;                             // 0..DFF-1
    int k = blockIdx.z;
    int a = i >> 6, b = i & 63;
    int x = j >> 5, y = j & 31;
    const float* c1 = C1 + (((size_t)(k * 64 + a) * 32 + x) * 16);
    const float* c2 = C2 + ((size_t)k * 16) * 64 * 32 + (size_t)b * 32 + y;
    float s = 0.f;
#pragma unroll
    for (int r = 0; r < RANK; r++)
        s += c1[r] * c2[(size_t)r * 64 * 32];
    g_W2[((size_t)k * DFF + i) * DMODEL + j] = s;
}

// ---------------------------------------------------------------------------
// Routing gates: one warp per token. logits = tokens . path_bases[k]; softmax.
// ---------------------------------------------------------------------------
__global__ void gates_kernel(const float* __restrict__ tokens,
                             const float* __restrict__ pb) {
    int n = blockIdx.x;
    int lane = threadIdx.x;
    float s0 = 0.f, s1 = 0.f, s2 = 0.f, s3 = 0.f;
    const float* t = tokens + (size_t)n * DMODEL;
    for (int i = lane; i < DMODEL; i += 32) {
        float tv = t[i];
        s0 += tv * pb[i];
        s1 += tv * pb[DMODEL + i];
        s2 += tv * pb[2 * DMODEL + i];
        s3 += tv * pb[3 * DMODEL + i];
    }
#pragma unroll
    for (int o = 16; o > 0; o >>= 1) {
        s0 += __shfl_down_sync(0xffffffffu, s0, o);
        s1 += __shfl_down_sync(0xffffffffu, s1, o);
        s2 += __shfl_down_sync(0xffffffffu, s2, o);
        s3 += __shfl_down_sync(0xffffffffu, s3, o);
    }
    if (lane == 0) {
        float m = fmaxf(fmaxf(s0, s1), fmaxf(s2, s3));
        float e0 = expf(s0 - m), e1 = expf(s1 - m), e2 = expf(s2 - m), e3 = expf(s3 - m);
        float inv = 1.f / (e0 + e1 + e2 + e3);
        g_gates[n * KP + 0] = e0 * inv;
        g_gates[n * KP + 1] = e1 * inv;
        g_gates[n * KP + 2] = e2 * inv;
        g_gates[n * KP + 3] = e3 * inv;
    }
}

__device__ __forceinline__ float gelu_tanh(float v) {
    // matches jax.nn.gelu(approximate=True)
    float c = 0.7978845608028654f;
    float t = tanhf(c * (v + 0.044715f * v * v * v));
    return 0.5f * v * (1.0f + t);
}

// ---------------------------------------------------------------------------
// GEMM1: h[k] = gelu(tokens @ W1[k]);  M=2048 N=4096 K=1024, grid.z = path
// 128x128 block tile, k-tile 16, 256 threads, 8x8 per-thread microtile.
// ---------------------------------------------------------------------------
__global__ __launch_bounds__(256, 2) void gemm1(const float* __restrict__ A) {
    int kp = blockIdx.z;
    const float* B = g_W1 + (size_t)kp * DMODEL * DFF;
    float* C = g_H + (size_t)kp * NTOK * DFF;
    const int m0 = blockIdx.y * 128;
    const int n0 = blockIdx.x * 128;

    __shared__ float As[16][132];  // transposed: As[kk][m]
    __shared__ float Bs[16][128];

    int tid = threadIdx.x;
    int tx = tid & 15, ty = tid >> 4;
    float acc[8][8];
#pragma unroll
    for (int i = 0; i < 8; i++)
#pragma unroll
        for (int j = 0; j < 8; j++) acc[i][j] = 0.f;

    for (int kt = 0; kt < DMODEL; kt += 16) {
#pragma unroll
        for (int u = 0; u < 2; u++) {  // A tile: 128 x 16 (512 float4)
            int f = (tid << 1) | u;
            int row = f >> 2, c4 = (f & 3) << 2;
            float4 v = *(const float4*)(A + (size_t)(m0 + row) * DMODEL + kt + c4);
            As[c4 + 0][row] = v.x; As[c4 + 1][row] = v.y;
            As[c4 + 2][row] = v.z; As[c4 + 3][row] = v.w;
        }
#pragma unroll
        for (int u = 0; u < 2; u++) {  // B tile: 16 x 128
            int f = (tid << 1) | u;
            int row = f >> 5, c4 = (f & 31) << 2;
            *(float4*)&Bs[row][c4] =
                *(const float4*)(B + (size_t)(kt + row) * DFF + n0 + c4);
        }
        __syncthreads();
#pragma unroll
        for (int kk = 0; kk < 16; kk++) {
            float a[8], b[8];
            *(float4*)(a)     = *(float4*)&As[kk][ty * 8];
            *(float4*)(a + 4) = *(float4*)&As[kk][ty * 8 + 4];
            *(float4*)(b)     = *(float4*)&Bs[kk][tx * 8];
            *(float4*)(b + 4) = *(float4*)&Bs[kk][tx * 8 + 4];
#pragma unroll
            for (int i = 0; i < 8; i++)
#pragma unroll
                for (int j = 0; j < 8; j++) acc[i][j] = fmaf(a[i], b[j], acc[i][j]);
        }
        __syncthreads();
    }
    // epilogue: gelu + store
#pragma unroll
    for (int i = 0; i < 8; i++) {
        size_t row = m0 + ty * 8 + i;
#pragma unroll
        for (int j4 = 0; j4 < 2; j4++) {
            float4 v;
            v.x = gelu_tanh(acc[i][j4 * 4 + 0]);
            v.y = gelu_tanh(acc[i][j4 * 4 + 1]);
            v.z = gelu_tanh(acc[i][j4 * 4 + 2]);
            v.w = gelu_tanh(acc[i][j4 * 4 + 3]);
            *(float4*)(C + row * DFF + n0 + tx * 8 + j4 * 4) = v;
        }
    }
}

// ---------------------------------------------------------------------------
// GEMM2 + routing: out[n,d] = sum_k gate[n,k]*(1+pw[k,d]) * (h[k,n,:] @ W2[k][:,d])
// gate folded into A tile, (1+pw) folded into B tile -> single accumulator.
// M=2048 N=1024 K=4*4096.
// ---------------------------------------------------------------------------
__global__ __launch_bounds__(256, 2) void gemm2(const float* __restrict__ pw,
                                                float* __restrict__ out) {
    const int m0 = blockIdx.y * 128;
    const int n0 = blockIdx.x * 128;

    __shared__ float As[16][132];
    __shared__ float Bs[16][128];

    int tid = threadIdx.x;
    int tx = tid & 15, ty = tid >> 4;
    float acc[8][8];
#pragma unroll
    for (int i = 0; i < 8; i++)
#pragma unroll
        for (int j = 0; j < 8; j++) acc[i][j] = 0.f;

    for (int kp = 0; kp < KP; kp++) {
        const float* A = g_H + (size_t)kp * NTOK * DFF;
        const float* B = g_W2 + (size_t)kp * DFF * DMODEL;
        for (int kt = 0; kt < DFF; kt += 16) {
#pragma unroll
            for (int u = 0; u < 2; u++) {  // A tile (scaled by gate)
                int f = (tid << 1) | u;
                int row = f >> 2, c4 = (f & 3) << 2;
                float g = g_gates[(m0 + row) * KP + kp];
                float4 v = *(const float4*)(A + (size_t)(m0 + row) * DFF + kt + c4);
                As[c4 + 0][row] = v.x * g; As[c4 + 1][row] = v.y * g;
                As[c4 + 2][row] = v.z * g; As[c4 + 3][row] = v.w * g;
            }
#pragma unroll
            for (int u = 0; u < 2; u++) {  // B tile (scaled by 1+pw)
                int f = (tid << 1) | u;
                int row = f >> 5, c4 = (f & 31) << 2;
                float4 v = *(const float4*)(B + (size_t)(kt + row) * DMODEL + n0 + c4);
                float4 w = *(const float4*)(pw + (size_t)kp * DMODEL + n0 + c4);
                v.x *= (1.f + w.x); v.y *= (1.f + w.y);
                v.z *= (1.f + w.z); v.w *= (1.f + w.w);
                *(float4*)&Bs[row][c4] = v;
            }
            __syncthreads();
#pragma unroll
            for (int kk = 0; kk < 16; kk++) {
                float a[8], b[8];
                *(float4*)(a)     = *(float4*)&As[kk][ty * 8];
                *(float4*)(a + 4) = *(float4*)&As[kk][ty * 8 + 4];
                *(float4*)(b)     = *(float4*)&Bs[kk][tx * 8];
                *(float4*)(b + 4) = *(float4*)&Bs[kk][tx * 8 + 4];
#pragma unroll
                for (int i = 0; i < 8; i++)
#pragma unroll
                    for (int j = 0; j < 8; j++) acc[i][j] = fmaf(a[i], b[j], acc[i][j]);
            }
            __syncthreads();
        }
    }
#pragma unroll
    for (int i = 0; i < 8; i++) {
        size_t row = m0 + ty * 8 + i;
#pragma unroll
        for (int j4 = 0; j4 < 2; j4++)
            *(float4*)(out + row * DMODEL + n0 + tx * 8 + j4 * 4) =
                *(float4*)&acc[i][j4 * 4];
    }
}

// ---------------------------------------------------------------------------
extern "C" void kernel_launch(void* const* d_in, const int* in_sizes, int n_in,
                              void* d_out, int out_size) {
    const float* tokens = (const float*)d_in[0];
    const float* G1     = (const float*)d_in[1];  // ffn1_core1 [4,32,64,16]
    const float* G2     = (const float*)d_in[2];  // ffn1_core2 [4,16,32,64]
    const float* C1     = (const float*)d_in[3];  // ffn2_core1 [4,64,32,16]
    const float* C2     = (const float*)d_in[4];  // ffn2_core2 [4,16,64,32]
    const float* pb     = (const float*)d_in[5];  // path_bases [4,1024]
    const float* pw     = (const float*)d_in[6];  // path_weights [4,1024]
    float* out = (float*)d_out;

    build_w1<<<dim3(DFF / 256, DMODEL, KP), 256>>>(G1, G2);
    build_w2<<<dim3(DMODEL / 256, DFF, KP), 256>>>(C1, C2);
    gates_kernel<<<NTOK, 32>>>(tokens, pb);
    gemm1<<<dim3(DFF / 128, NTOK / 128, KP), 256>>>(tokens);
    gemm2<<<dim3(DMODEL / 128, NTOK / 128), 256>>>(pw, out);
}

// round 13
// speedup vs baseline: 3.6289x; 3.6281x over previous
#include <cuda_runtime.h>
#include <math.h>
#include <stdint.h>

#define KP 4
#define DMODEL 1024
#define DFF 4096
#define NTOK 2048

#define BM 128
#define BN 128
#define BK 32
#define ROWF 36                       // smem row stride in floats (144B, 16B aligned, bank-safe)
#define STAGE_F (2 * 128 * ROWF)      // A(128x36) + B(128x36) floats
#define STAGE_B (STAGE_F * 4)         // 36864 bytes
#define NSTAGE 4
#define SMEM_DYN (NSTAGE * STAGE_B)   // 147456

// ---- device scratch (allocation-free rule) ----
__device__ __align__(256) float g_T  [(size_t)NTOK * DMODEL];       // tf32-rounded tokens
__device__ __align__(256) float g_W1t[(size_t)KP * DFF * DMODEL];   // [k][n][kdim] K-major, tf32
__device__ __align__(256) float g_W2t[(size_t)KP * DMODEL * DFF];   // [k][d][f]   K-major, tf32, pw folded
__device__ __align__(256) float g_H  [(size_t)KP * NTOK * DFF];     // [k][m][f]   gate*gelu, tf32
__device__ __align__(256) float g_part[(size_t)KP * NTOK * DMODEL];
__device__ __align__(256) float g_gates[NTOK * KP];

// =============== helpers ===============
__device__ __forceinline__ uint32_t smem_u32(const void* p) {
    uint32_t a;
    asm("{ .reg .u64 t; cvta.to.shared.u64 t, %1; cvt.u32.u64 %0, t; }" : "=r"(a) : "l"(p));
    return a;
}
__device__ __forceinline__ void cpa16(uint32_t dst, const float* src) {
    asm volatile("cp.async.cg.shared.global [%0], [%1], 16;" :: "r"(dst), "l"(src) : "memory");
}
__device__ __forceinline__ void cpa_commit() { asm volatile("cp.async.commit_group;" ::: "memory"); }
__device__ __forceinline__ float to_tf32(float x) {
    float y;
    asm("cvt.rna.tf32.f32 %0, %1;" : "=f"(y) : "f"(x));
    return y;
}
__device__ __forceinline__ float gelu_tanh(float v) {
    float c = 0.7978845608028654f;
    float t = tanhf(c * (v + 0.044715f * v * v * v));
    return 0.5f * v * (1.0f + t);
}

// =============== tokens -> tf32 ===============
__global__ void round_tokens(const float* __restrict__ t) {
    size_t i = ((size_t)blockIdx.x * 256 + threadIdx.x) * 4;
    float4 v = *(const float4*)(t + i);
    v.x = to_tf32(v.x); v.y = to_tf32(v.y); v.z = to_tf32(v.z); v.w = to_tf32(v.w);
    *(float4*)(g_T + i) = v;
}

// =============== weight expansion (tf32-rounded, K-major) ===============
// W1t[kp][x*64+y][a*32+b] = sum_r G1[kp,a,x,r]*G2[kp,r,b,y]
__global__ void build_w1t(const float* __restrict__ G1, const float* __restrict__ G2) {
    __shared__ float G2s[16 * 32 * 17];
    __shared__ float G1s[32 * 16];
    int tid = threadIdx.x;
    int x = blockIdx.x, y0 = blockIdx.y * 16, kp = blockIdx.z;
    for (int e = tid; e < 8192; e += 256) {
        int r = e >> 9, b = (e >> 4) & 31, yl = e & 15;
        G2s[(r * 32 + b) * 17 + yl] = G2[((size_t)(kp * 16 + r) * 32 + b) * 64 + y0 + yl];
    }
    for (int e = tid; e < 512; e += 256) {
        int a = e >> 4, r = e & 15;
        G1s[e] = G1[((size_t)(kp * 32 + a) * 64 + x) * 16 + r];
    }
    __syncthreads();
#pragma unroll
    for (int i = 0; i < 4; i++) {       // k in [0, DMODEL): 256 threads x 4
        int k = tid + 256 * i;  // a*32+b
        int a = k >> 5, b = k & 31;
        float acc[16];
#pragma unroll
        for (int y = 0; y < 16; y++) acc[y] = 0.f;
#pragma unroll
        for (int r = 0; r < 16; r++) {
            float g1 = G1s[a * 16 + r];
#pragma unroll
            for (int y = 0; y < 16; y++)
                acc[y] = fmaf(g1, G2s[(r * 32 + b) * 17 + y], acc[y]);
        }
#pragma unroll
        for (int y = 0; y < 16; y++)
            g_W1t[((size_t)kp * DFF + x * 64 + y0 + y) * DMODEL + k] = to_tf32(acc[y]);
    }
}

// W2t[kp][x*32+y][a*64+b] = (1+pw[kp][d]) * sum_r C1[kp,a,x,r]*C2[kp,r,b,y]
__global__ void build_w2t(const float* __restrict__ C1, const float* __restrict__ C2,
                          const float* __restrict__ pw) {
    __shared__ float C2s[16 * 64 * 9];
    __shared__ float C1s[64 * 16];
    int tid = threadIdx.x;
    int x = blockIdx.x, y0 = blockIdx.y * 8, kp = blockIdx.z;
    for (int e = tid; e < 8192; e += 256) {
        int r = e >> 9, b = (e >> 3) & 63, yl = e & 7;
        C2s[(r * 64 + b) * 9 + yl] = C2[((size_t)(kp * 16 + r) * 64 + b) * 32 + y0 + yl];
    }
    for (int e = tid; e < 1024; e += 256) {
        int a = e >> 4, r = e & 15;
        C1s[e] = C1[((size_t)(kp * 64 + a) * 32 + x) * 16 + r];
    }
    __syncthreads();
#pragma unroll
    for (int i = 0; i < 16; i++) {      // f in [0, DFF): 256 threads x 16
        int f = tid + 256 * i;  // a*64+b
        int a = f >> 6, b = f & 63;
        float acc[8];
#pragma unroll
        for (int y = 0; y < 8; y++) acc[y] = 0.f;
#pragma unroll
        for (int r = 0; r < 16; r++) {
            float c1 = C1s[a * 16 + r];
#pragma unroll
            for (int y = 0; y < 8; y++)
                acc[y] = fmaf(c1, C2s[(r * 64 + b) * 9 + y], acc[y]);
        }
#pragma unroll
        for (int y = 0; y < 8; y++) {
            int d = x * 32 + y0 + y;
            g_W2t[((size_t)kp * DMODEL + d) * DFF + f] =
                to_tf32(acc[y] * (1.f + pw[kp * DMODEL + d]));
        }
    }
}

// =============== routing gates ===============
__global__ void gates_kernel(const float* __restrict__ tokens, const float* __restrict__ pb) {
    int n = blockIdx.x;
    int lane = threadIdx.x;
    float s0 = 0.f, s1 = 0.f, s2 = 0.f, s3 = 0.f;
    const float* t = tokens + (size_t)n * DMODEL;
    for (int i = lane; i < DMODEL; i += 32) {
        float tv = t[i];
        s0 += tv * pb[i];
        s1 += tv * pb[DMODEL + i];
        s2 += tv * pb[2 * DMODEL + i];
        s3 += tv * pb[3 * DMODEL + i];
    }
#pragma unroll
    for (int o = 16; o > 0; o >>= 1) {
        s0 += __shfl_down_sync(0xffffffffu, s0, o);
        s1 += __shfl_down_sync(0xffffffffu, s1, o);
        s2 += __shfl_down_sync(0xffffffffu, s2, o);
        s3 += __shfl_down_sync(0xffffffffu, s3, o);
    }
    if (lane == 0) {
        float m = fmaxf(fmaxf(s0, s1), fmaxf(s2, s3));
        float e0 = expf(s0 - m), e1 = expf(s1 - m), e2 = expf(s2 - m), e3 = expf(s3 - m);
        float inv = 1.f / (e0 + e1 + e2 + e3);
        g_gates[n * KP + 0] = e0 * inv;
        g_gates[n * KP + 1] = e1 * inv;
        g_gates[n * KP + 2] = e2 * inv;
        g_gates[n * KP + 3] = e3 * inv;
    }
}

// =============== tf32 mma.sync GEMM ===============
__device__ __forceinline__ void fill_tile(uint32_t sbase, int buf,
                                          const float* __restrict__ A, int lda,
                                          const float* __restrict__ B, int ldb,
                                          int m0, int n0, int k0, int tid) {
    uint32_t ab = sbase + buf * STAGE_B;
    uint32_t bb = ab + 128 * ROWF * 4;
#pragma unroll
    for (int u = 0; u < 4; u++) {
        int idx = tid + 256 * u;              // 0..1023
        int row = idx >> 3, seg = idx & 7;
        cpa16(ab + row * (ROWF * 4) + seg * 16, A + (size_t)(m0 + row) * lda + k0 + seg * 4);
        cpa16(bb + row * (ROWF * 4) + seg * 16, B + (size_t)(n0 + row) * ldb + k0 + seg * 4);
    }
}

// MODE 0: g_T @ W1t -> gate*gelu -> g_H (tf32-rounded)
// MODE 1: g_H @ W2t -> g_part
template <int MODE>
__global__ __launch_bounds__(256, 1) void gemm_tc(void) {
    extern __shared__ char smb[];
    uint32_t sbase = smem_u32(smb);

    int tid = threadIdx.x;
    int wid = tid >> 5, lane = tid & 31;
    int g = lane >> 2, tig = lane & 3;
    int kp = blockIdx.z;
    int m0 = blockIdx.y * BM, n0 = blockIdx.x * BN;

    const int lda = (MODE == 0) ? DMODEL : DFF;
    const int ldb = (MODE == 0) ? DMODEL : DFF;
    const int ldc = (MODE == 0) ? DFF : DMODEL;
    const int Ktot = (MODE == 0) ? DMODEL : DFF;
    const float* A = (MODE == 0) ? g_T : (g_H + (size_t)kp * NTOK * DFF);
    const float* B = (MODE == 0) ? (g_W1t + (size_t)kp * DFF * DMODEL)
                                 : (g_W2t + (size_t)kp * DMODEL * DFF);
    float* C = (MODE == 0) ? (g_H + (size_t)kp * NTOK * DFF)
                           : (g_part + (size_t)kp * NTOK * DMODEL);

    const int rm = (wid >> 2) * 64;   // warp m offset (0,64)
    const int cn = (wid & 3) * 32;    // warp n offset (0..96)

    float d[4][4][4];
#pragma unroll
    for (int i = 0; i < 4; i++)
#pragma unroll
        for (int j = 0; j < 4; j++)
#pragma unroll
            for (int q = 0; q < 4; q++) d[i][j][q] = 0.f;

    const int NK = Ktot / BK;
    fill_tile(sbase, 0, A, lda, B, ldb, m0, n0, 0, tid); cpa_commit();
    fill_tile(sbase, 1, A, lda, B, ldb, m0, n0, BK, tid); cpa_commit();
    fill_tile(sbase, 2, A, lda, B, ldb, m0, n0, 2 * BK, tid); cpa_commit();

    for (int kt = 0; kt < NK; kt++) {
        asm volatile("cp.async.wait_group 2;" ::: "memory");
        __syncthreads();
        int buf = kt & 3;
        const float* As = (const float*)(smb + buf * STAGE_B);
        const float* Bs = As + 128 * ROWF;
#pragma unroll
        for (int ks = 0; ks < 4; ks++) {
            int kk = ks * 8 + tig;
            uint32_t a[4][4], b[4][2];
#pragma unroll
            for (int mb = 0; mb < 4; mb++) {
                const float* p = As + (rm + mb * 16 + g) * ROWF + kk;
                a[mb][0] = __float_as_uint(p[0]);
                a[mb][1] = __float_as_uint(p[8 * ROWF]);
                a[mb][2] = __float_as_uint(p[4]);
                a[mb][3] = __float_as_uint(p[8 * ROWF + 4]);
            }
#pragma unroll
            for (int nb = 0; nb < 4; nb++) {
                const float* p = Bs + (cn + nb * 8 + g) * ROWF + kk;
                b[nb][0] = __float_as_uint(p[0]);
                b[nb][1] = __float_as_uint(p[4]);
            }
#pragma unroll
            for (int mb = 0; mb < 4; mb++)
#pragma unroll
                for (int nb = 0; nb < 4; nb++)
                    asm volatile(
                        "mma.sync.aligned.m16n8k8.row.col.f32.tf32.tf32.f32 "
                        "{%0,%1,%2,%3}, {%4,%5,%6,%7}, {%8,%9}, {%0,%1,%2,%3};"
                        : "+f"(d[mb][nb][0]), "+f"(d[mb][nb][1]),
                          "+f"(d[mb][nb][2]), "+f"(d[mb][nb][3])
                        : "r"(a[mb][0]), "r"(a[mb][1]), "r"(a[mb][2]), "r"(a[mb][3]),
                          "r"(b[nb][0]), "r"(b[nb][1]));
        }
        if (kt + 3 < NK)
            fill_tile(sbase, (kt + 3) & 3, A, lda, B, ldb, m0, n0, (kt + 3) * BK, tid);
        cpa_commit();
    }

    __syncthreads();  // mainloop fully done; reuse smem for epilogue staging

    float* ws = (float*)smb + wid * (16 * ROWF);  // per-warp 16x36 floats
#pragma unroll
    for (int mb = 0; mb < 4; mb++) {
        int grow = m0 + rm + mb * 16;
        float gate_lo = 0.f, gate_hi = 0.f;
        if (MODE == 0) {
            gate_lo = g_gates[(size_t)(grow + g) * KP + kp];
            gate_hi = g_gates[(size_t)(grow + g + 8) * KP + kp];
        }
#pragma unroll
        for (int nb = 0; nb < 4; nb++) {
            int c = nb * 8 + tig * 2;
            float v0 = d[mb][nb][0], v1 = d[mb][nb][1];
            float v2 = d[mb][nb][2], v3 = d[mb][nb][3];
            if (MODE == 0) {
                v0 = to_tf32(gate_lo * gelu_tanh(v0));
                v1 = to_tf32(gate_lo * gelu_tanh(v1));
                v2 = to_tf32(gate_hi * gelu_tanh(v2));
                v3 = to_tf32(gate_hi * gelu_tanh(v3));
            }
            ws[g * ROWF + c] = v0;       ws[g * ROWF + c + 1] = v1;
            ws[(g + 8) * ROWF + c] = v2; ws[(g + 8) * ROWF + c + 1] = v3;
        }
        __syncwarp();
        int row = lane >> 1, half = lane & 1;
        const float* src = ws + row * ROWF + half * 16;
        float* dst = C + (size_t)(grow + row) * ldc + n0 + cn + half * 16;
#pragma unroll
        for (int q = 0; q < 4; q++)
            *(float4*)(dst + q * 4) = *(const float4*)(src + q * 4);
        __syncwarp();
    }
}

// =============== final reduce over 4 path partials ===============
__global__ void reduce_out(float* __restrict__ out) {
    const size_t S = (size_t)NTOK * DMODEL;
    size_t i = ((size_t)blockIdx.x * 256 + threadIdx.x) * 4;
    float4 a = *(const float4*)(g_part + i);
    float4 b = *(const float4*)(g_part + S + i);
    float4 c = *(const float4*)(g_part + 2 * S + i);
    float4 d = *(const float4*)(g_part + 3 * S + i);
    float4 o;
    o.x = a.x + b.x + c.x + d.x;
    o.y = a.y + b.y + c.y + d.y;
    o.z = a.z + b.z + c.z + d.z;
    o.w = a.w + b.w + c.w + d.w;
    *(float4*)(out + i) = o;
}

// ===========================================================================
extern "C" void kernel_launch(void* const* d_in, const int* in_sizes, int n_in,
                              void* d_out, int out_size) {
    const float* tokens = (const float*)d_in[0];
    const float* G1 = (const float*)d_in[1];  // [4,32,64,16]
    const float* G2 = (const float*)d_in[2];  // [4,16,32,64]
    const float* C1 = (const float*)d_in[3];  // [4,64,32,16]
    const float* C2 = (const float*)d_in[4];  // [4,16,64,32]
    const float* pb = (const float*)d_in[5];  // [4,1024]
    const float* pw = (const float*)d_in[6];  // [4,1024]
    float* out = (float*)d_out;

    // host-side, non-stream API: safe under graph capture, no static guard
    cudaFuncSetAttribute(gemm_tc<0>, cudaFuncAttributeMaxDynamicSharedMemorySize, SMEM_DYN);
    cudaFuncSetAttribute(gemm_tc<1>, cudaFuncAttributeMaxDynamicSharedMemorySize, SMEM_DYN);

    round_tokens<<<(NTOK * DMODEL / 4) / 256, 256>>>(tokens);
    build_w1t<<<dim3(64, 4, KP), 256>>>(G1, G2);
    build_w2t<<<dim3(32, 4, KP), 256>>>(C1, C2, pw);
    gates_kernel<<<NTOK, 32>>>(tokens, pb);
    gemm_tc<0><<<dim3(DFF / BN, NTOK / BM, KP), 256, SMEM_DYN>>>();
    gemm_tc<1><<<dim3(DMODEL / BN, NTOK / BM, KP), 256, SMEM_DYN>>>();
    reduce_out<<<(NTOK * DMODEL / 4) / 256, 256>>>(out);
}

// round 15
// speedup vs baseline: 7.2481x; 1.9973x over previous
#include <cuda_runtime.h>
#include <cuda_fp16.h>
#include <math.h>
#include <stdint.h>

#define KP 4
#define DMODEL 1024
#define DFF 4096
#define NTOK 2048

#define BM 128
#define BN 128
#define BK 64                          // 4 x k16 steps
#define ROWH 72                        // smem row stride in halves (144B)
#define TILE_B (128 * ROWH * 2)        // one operand tile: 18432 B
#define STAGE_B (2 * TILE_B)           // A + B: 36864 B
#define NSTAGE 3
#define SMEM_DYN (NSTAGE * STAGE_B)    // 110592 B -> 2 CTAs/SM

// ---- device scratch (allocation-free rule) ----
__device__ __align__(256) __half g_T  [(size_t)NTOK * DMODEL];       // fp16 tokens
__device__ __align__(256) __half g_W1t[(size_t)KP * DFF * DMODEL];   // [k][n][kdim] K-major fp16
__device__ __align__(256) __half g_W2t[(size_t)KP * DMODEL * DFF];   // [k][d][f] K-major fp16, pw folded
__device__ __align__(256) __half g_H  [(size_t)KP * NTOK * DFF];     // [k][m][f] gate*gelu fp16
__device__ __align__(256) float  g_part[(size_t)KP * NTOK * DMODEL]; // fp32 partials
__device__ __align__(256) float  g_gates[NTOK * KP];

// =============== helpers ===============
__device__ __forceinline__ uint32_t smem_u32(const void* p) {
    uint32_t a;
    asm("{ .reg .u64 t; cvta.to.shared.u64 t, %1; cvt.u32.u64 %0, t; }" : "=r"(a) : "l"(p));
    return a;
}
__device__ __forceinline__ void cpa16(uint32_t dst, const void* src) {
    asm volatile("cp.async.cg.shared.global [%0], [%1], 16;" :: "r"(dst), "l"(src) : "memory");
}
__device__ __forceinline__ void cpa_commit() { asm volatile("cp.async.commit_group;" ::: "memory"); }
__device__ __forceinline__ float gelu_tanh(float v) {
    float c = 0.7978845608028654f;
    float t = tanhf(c * (v + 0.044715f * v * v * v));
    return 0.5f * v * (1.0f + t);
}

// =============== tokens -> fp16 ===============
__global__ void round_tokens(const float* __restrict__ t) {
    size_t i = ((size_t)blockIdx.x * 256 + threadIdx.x) * 4;
    float4 v = *(const float4*)(t + i);
    *(__half2*)(g_T + i)     = __floats2half2_rn(v.x, v.y);
    *(__half2*)(g_T + i + 2) = __floats2half2_rn(v.z, v.w);
}

// =============== weight expansion (fp16, K-major) ===============
// W1t[kp][x*64+y][a*32+b] = sum_r G1[kp,a,x,r]*G2[kp,r,b,y]
__global__ void build_w1t(const float* __restrict__ G1, const float* __restrict__ G2) {
    __shared__ float G2s[16 * 32 * 17];
    __shared__ float G1s[32 * 16];
    int tid = threadIdx.x;
    int x = blockIdx.x, y0 = blockIdx.y * 16, kp = blockIdx.z;
    for (int e = tid; e < 8192; e += 256) {
        int r = e >> 9, b = (e >> 4) & 31, yl = e & 15;
        G2s[(r * 32 + b) * 17 + yl] = G2[((size_t)(kp * 16 + r) * 32 + b) * 64 + y0 + yl];
    }
    for (int e = tid; e < 512; e += 256) {
        int a = e >> 4, r = e & 15;
        G1s[e] = G1[((size_t)(kp * 32 + a) * 64 + x) * 16 + r];
    }
    __syncthreads();
#pragma unroll
    for (int i = 0; i < 4; i++) {       // k in [0, DMODEL)
        int k = tid + 256 * i;          // a*32+b
        int a = k >> 5, b = k & 31;
        float acc[16];
#pragma unroll
        for (int y = 0; y < 16; y++) acc[y] = 0.f;
#pragma unroll
        for (int r = 0; r < 16; r++) {
            float g1 = G1s[a * 16 + r];
#pragma unroll
            for (int y = 0; y < 16; y++)
                acc[y] = fmaf(g1, G2s[(r * 32 + b) * 17 + y], acc[y]);
        }
#pragma unroll
        for (int y = 0; y < 16; y++)
            g_W1t[((size_t)kp * DFF + x * 64 + y0 + y) * DMODEL + k] = __float2half_rn(acc[y]);
    }
}

// W2t[kp][x*32+y][a*64+b] = (1+pw[kp][d]) * sum_r C1[kp,a,x,r]*C2[kp,r,b,y]
__global__ void build_w2t(const float* __restrict__ C1, const float* __restrict__ C2,
                          const float* __restrict__ pw) {
    __shared__ float C2s[16 * 64 * 9];
    __shared__ float C1s[64 * 16];
    int tid = threadIdx.x;
    int x = blockIdx.x, y0 = blockIdx.y * 8, kp = blockIdx.z;
    for (int e = tid; e < 8192; e += 256) {
        int r = e >> 9, b = (e >> 3) & 63, yl = e & 7;
        C2s[(r * 64 + b) * 9 + yl] = C2[((size_t)(kp * 16 + r) * 64 + b) * 32 + y0 + yl];
    }
    for (int e = tid; e < 1024; e += 256) {
        int a = e >> 4, r = e & 15;
        C1s[e] = C1[((size_t)(kp * 64 + a) * 32 + x) * 16 + r];
    }
    __syncthreads();
#pragma unroll
    for (int i = 0; i < 16; i++) {      // f in [0, DFF)
        int f = tid + 256 * i;          // a*64+b
        int a = f >> 6, b = f & 63;
        float acc[8];
#pragma unroll
        for (int y = 0; y < 8; y++) acc[y] = 0.f;
#pragma unroll
        for (int r = 0; r < 16; r++) {
            float c1 = C1s[a * 16 + r];
#pragma unroll
            for (int y = 0; y < 8; y++)
                acc[y] = fmaf(c1, C2s[(r * 64 + b) * 9 + y], acc[y]);
        }
#pragma unroll
        for (int y = 0; y < 8; y++) {
            int d = x * 32 + y0 + y;
            g_W2t[((size_t)kp * DMODEL + d) * DFF + f] =
                __float2half_rn(acc[y] * (1.f + pw[kp * DMODEL + d]));
        }
    }
}

// =============== routing gates ===============
__global__ void gates_kernel(const float* __restrict__ tokens, const float* __restrict__ pb) {
    int n = blockIdx.x;
    int lane = threadIdx.x;
    float s0 = 0.f, s1 = 0.f, s2 = 0.f, s3 = 0.f;
    const float* t = tokens + (size_t)n * DMODEL;
    for (int i = lane; i < DMODEL; i += 32) {
        float tv = t[i];
        s0 += tv * pb[i];
        s1 += tv * pb[DMODEL + i];
        s2 += tv * pb[2 * DMODEL + i];
        s3 += tv * pb[3 * DMODEL + i];
    }
#pragma unroll
    for (int o = 16; o > 0; o >>= 1) {
        s0 += __shfl_down_sync(0xffffffffu, s0, o);
        s1 += __shfl_down_sync(0xffffffffu, s1, o);
        s2 += __shfl_down_sync(0xffffffffu, s2, o);
        s3 += __shfl_down_sync(0xffffffffu, s3, o);
    }
    if (lane == 0) {
        float m = fmaxf(fmaxf(s0, s1), fmaxf(s2, s3));
        float e0 = expf(s0 - m), e1 = expf(s1 - m), e2 = expf(s2 - m), e3 = expf(s3 - m);
        float inv = 1.f / (e0 + e1 + e2 + e3);
        g_gates[n * KP + 0] = e0 * inv;
        g_gates[n * KP + 1] = e1 * inv;
        g_gates[n * KP + 2] = e2 * inv;
        g_gates[n * KP + 3] = e3 * inv;
    }
}

// =============== fp16 mma.sync GEMM ===============
__device__ __forceinline__ void fill_tile(uint32_t sbase, int buf,
                                          const __half* __restrict__ A, int lda,
                                          const __half* __restrict__ B, int ldb,
                                          int m0, int n0, int k0, int tid) {
    uint32_t ab = sbase + buf * STAGE_B;
    uint32_t bb = ab + TILE_B;
#pragma unroll
    for (int u = 0; u < 4; u++) {
        int idx = tid + 256 * u;              // 0..1023
        int row = idx >> 3, seg = idx & 7;
        cpa16(ab + row * (ROWH * 2) + seg * 16, A + (size_t)(m0 + row) * lda + k0 + seg * 8);
        cpa16(bb + row * (ROWH * 2) + seg * 16, B + (size_t)(n0 + row) * ldb + k0 + seg * 8);
    }
}

// MODE 0: g_T @ W1t -> gate*gelu -> g_H (fp16)
// MODE 1: g_H @ W2t -> g_part (fp32)
template <int MODE>
__global__ __launch_bounds__(256, 2) void gemm_tc(void) {
    extern __shared__ char smb[];
    uint32_t sbase = smem_u32(smb);

    int tid = threadIdx.x;
    int wid = tid >> 5, lane = tid & 31;
    int g = lane >> 2, tig = lane & 3;
    int kp = blockIdx.z;
    int m0 = blockIdx.y * BM, n0 = blockIdx.x * BN;

    const int lda = (MODE == 0) ? DMODEL : DFF;
    const int ldb = (MODE == 0) ? DMODEL : DFF;
    const int Ktot = (MODE == 0) ? DMODEL : DFF;
    const __half* A = (MODE == 0) ? g_T : (g_H + (size_t)kp * NTOK * DFF);
    const __half* B = (MODE == 0) ? (g_W1t + (size_t)kp * DFF * DMODEL)
                                  : (g_W2t + (size_t)kp * DMODEL * DFF);

    const int rm = (wid >> 2) * 64;   // warp m offset (0,64)
    const int cn = (wid & 3) * 32;    // warp n offset (0..96)

    float d[4][4][4];
#pragma unroll
    for (int i = 0; i < 4; i++)
#pragma unroll
        for (int j = 0; j < 4; j++)
#pragma unroll
            for (int q = 0; q < 4; q++) d[i][j][q] = 0.f;

    const int NK = Ktot / BK;
    fill_tile(sbase, 0, A, lda, B, ldb, m0, n0, 0, tid); cpa_commit();
    fill_tile(sbase, 1, A, lda, B, ldb, m0, n0, BK, tid); cpa_commit();

    for (int kt = 0; kt < NK; kt++) {
        asm volatile("cp.async.wait_group 1;" ::: "memory");
        __syncthreads();
        int buf = kt % 3;
        const __half* As = (const __half*)(smb + buf * STAGE_B);
        const __half* Bs = (const __half*)(smb + buf * STAGE_B + TILE_B);
#pragma unroll
        for (int ks = 0; ks < 4; ks++) {
            int kk = ks * 16 + 2 * tig;
            uint32_t a[4][4], b[4][2];
#pragma unroll
            for (int mb = 0; mb < 4; mb++) {
                const __half* p = As + (rm + mb * 16 + g) * ROWH + kk;
                a[mb][0] = *(const uint32_t*)(p);
                a[mb][1] = *(const uint32_t*)(p + 8 * ROWH);
                a[mb][2] = *(const uint32_t*)(p + 8);
                a[mb][3] = *(const uint32_t*)(p + 8 * ROWH + 8);
            }
#pragma unroll
            for (int nb = 0; nb < 4; nb++) {
                const __half* p = Bs + (cn + nb * 8 + g) * ROWH + kk;
                b[nb][0] = *(const uint32_t*)(p);
                b[nb][1] = *(const uint32_t*)(p + 8);
            }
#pragma unroll
            for (int mb = 0; mb < 4; mb++)
#pragma unroll
                for (int nb = 0; nb < 4; nb++)
                    asm volatile(
                        "mma.sync.aligned.m16n8k16.row.col.f32.f16.f16.f32 "
                        "{%0,%1,%2,%3}, {%4,%5,%6,%7}, {%8,%9}, {%0,%1,%2,%3};"
                        : "+f"(d[mb][nb][0]), "+f"(d[mb][nb][1]),
                          "+f"(d[mb][nb][2]), "+f"(d[mb][nb][3])
                        : "r"(a[mb][0]), "r"(a[mb][1]), "r"(a[mb][2]), "r"(a[mb][3]),
                          "r"(b[nb][0]), "r"(b[nb][1]));
        }
        if (kt + 2 < NK)
            fill_tile(sbase, (kt + 2) % 3, A, lda, B, ldb, m0, n0, (kt + 2) * BK, tid);
        cpa_commit();
    }

    __syncthreads();  // mainloop done; reuse smem for epilogue

    if (MODE == 0) {
        // gate * gelu -> fp16 g_H, coalesced via smem transpose.
        // Warp tile = 16 rows x 32 cols per mb. Writer fills cols [0,32) of ws.
        // Reader: 16 rows x 2 parts x 16 halves = exactly 32 cols.
        __half* C = g_H + (size_t)kp * NTOK * DFF;
        __half* ws = (__half*)smb + wid * (16 * ROWH);
#pragma unroll
        for (int mb = 0; mb < 4; mb++) {
            int grow = m0 + rm + mb * 16;
            float gate_lo = g_gates[(size_t)(grow + g) * KP + kp];
            float gate_hi = g_gates[(size_t)(grow + g + 8) * KP + kp];
#pragma unroll
            for (int nb = 0; nb < 4; nb++) {
                int c = nb * 8 + 2 * tig;
                float v0 = gate_lo * gelu_tanh(d[mb][nb][0]);
                float v1 = gate_lo * gelu_tanh(d[mb][nb][1]);
                float v2 = gate_hi * gelu_tanh(d[mb][nb][2]);
                float v3 = gate_hi * gelu_tanh(d[mb][nb][3]);
                *(__half2*)(ws + g * ROWH + c) = __floats2half2_rn(v0, v1);
                *(__half2*)(ws + (g + 8) * ROWH + c) = __floats2half2_rn(v2, v3);
            }
            __syncwarp();
            int row = lane >> 1, part = lane & 1;
            const uint4* src = (const uint4*)(ws + row * ROWH + part * 16);
            __half* dst = C + (size_t)(grow + row) * DFF + n0 + cn + part * 16;
#pragma unroll
            for (int q = 0; q < 2; q++)
                *(uint4*)(dst + q * 8) = src[q];
            __syncwarp();
        }
    } else {
        // fp32 partials, coalesced via smem transpose (16 rows x 2 halves x 16 floats = 32 cols)
        float* C = g_part + (size_t)kp * NTOK * DMODEL;
        float* ws = (float*)smb + wid * (16 * 36);
#pragma unroll
        for (int mb = 0; mb < 4; mb++) {
            int grow = m0 + rm + mb * 16;
#pragma unroll
            for (int nb = 0; nb < 4; nb++) {
                int c = nb * 8 + tig * 2;
                ws[g * 36 + c] = d[mb][nb][0];
                ws[g * 36 + c + 1] = d[mb][nb][1];
                ws[(g + 8) * 36 + c] = d[mb][nb][2];
                ws[(g + 8) * 36 + c + 1] = d[mb][nb][3];
            }
            __syncwarp();
            int row = lane >> 1, half = lane & 1;
            const float* src = ws + row * 36 + half * 16;
            float* dst = C + (size_t)(grow + row) * DMODEL + n0 + cn + half * 16;
#pragma unroll
            for (int q = 0; q < 4; q++)
                *(float4*)(dst + q * 4) = *(const float4*)(src + q * 4);
            __syncwarp();
        }
    }
}

// =============== final reduce over 4 path partials ===============
__global__ void reduce_out(float* __restrict__ out) {
    const size_t S = (size_t)NTOK * DMODEL;
    size_t i = ((size_t)blockIdx.x * 256 + threadIdx.x) * 4;
    float4 a = *(const float4*)(g_part + i);
    float4 b = *(const float4*)(g_part + S + i);
    float4 c = *(const float4*)(g_part + 2 * S + i);
    float4 d = *(const float4*)(g_part + 3 * S + i);
    float4 o;
    o.x = a.x + b.x + c.x + d.x;
    o.y = a.y + b.y + c.y + d.y;
    o.z = a.z + b.z + c.z + d.z;
    o.w = a.w + b.w + c.w + d.w;
    *(float4*)(out + i) = o;
}

// ===========================================================================
extern "C" void kernel_launch(void* const* d_in, const int* in_sizes, int n_in,
                              void* d_out, int out_size) {
    const float* tokens = (const float*)d_in[0];
    const float* G1 = (const float*)d_in[1];  // [4,32,64,16]
    const float* G2 = (const float*)d_in[2];  // [4,16,32,64]
    const float* C1 = (const float*)d_in[3];  // [4,64,32,16]
    const float* C2 = (const float*)d_in[4];  // [4,16,64,32]
    const float* pb = (const float*)d_in[5];  // [4,1024]
    const float* pw = (const float*)d_in[6];  // [4,1024]
    float* out = (float*)d_out;

    cudaFuncSetAttribute(gemm_tc<0>, cudaFuncAttributeMaxDynamicSharedMemorySize, SMEM_DYN);
    cudaFuncSetAttribute(gemm_tc<1>, cudaFuncAttributeMaxDynamicSharedMemorySize, SMEM_DYN);

    round_tokens<<<(NTOK * DMODEL / 4) / 256, 256>>>(tokens);
    build_w1t<<<dim3(64, 4, KP), 256>>>(G1, G2);
    build_w2t<<<dim3(32, 4, KP), 256>>>(C1, C2, pw);
    gates_kernel<<<NTOK, 32>>>(tokens, pb);
    gemm_tc<0><<<dim3(DFF / BN, NTOK / BM, KP), 256, SMEM_DYN>>>();
    gemm_tc<1><<<dim3(DMODEL / BN, NTOK / BM, KP), 256, SMEM_DYN>>>();
    reduce_out<<<(NTOK * DMODEL / 4) / 256, 256>>>(out);
}

// round 16
// speedup vs baseline: 8.0109x; 1.1052x over previous
#include <cuda_runtime.h>
#include <cuda_fp16.h>
#include <math.h>
#include <stdint.h>

#define KP 4
#define DMODEL 1024
#define DFF 4096
#define NTOK 2048

#define BM 128
#define BN 128
#define BK 64                          // 4 x k16 steps
#define ROWH 72                        // smem row stride in halves (144B)
#define TILE_B (128 * ROWH * 2)        // one operand tile: 18432 B
#define STAGE_B (2 * TILE_B)           // A + B: 36864 B
#define NSTAGE 3
#define SMEM_DYN (NSTAGE * STAGE_B)    // 110592 B -> 2 CTAs/SM

// ---- device scratch (allocation-free rule) ----
__device__ __align__(256) __half g_T  [(size_t)NTOK * DMODEL];       // fp16 tokens
__device__ __align__(256) __half g_W1t[(size_t)KP * DFF * DMODEL];   // [k][n][kdim] K-major fp16
__device__ __align__(256) __half g_W2t[(size_t)KP * DMODEL * DFF];   // [k][d][f] K-major fp16, pw folded
__device__ __align__(256) __half g_H  [(size_t)KP * NTOK * DFF];     // [k][m][f] gate*gelu fp16
__device__ __align__(256) float  g_gates[NTOK * KP];

// =============== helpers ===============
__device__ __forceinline__ uint32_t smem_u32(const void* p) {
    uint32_t a;
    asm("{ .reg .u64 t; cvta.to.shared.u64 t, %1; cvt.u32.u64 %0, t; }" : "=r"(a) : "l"(p));
    return a;
}
__device__ __forceinline__ void cpa16(uint32_t dst, const void* src) {
    asm volatile("cp.async.cg.shared.global [%0], [%1], 16;" :: "r"(dst), "l"(src) : "memory");
}
__device__ __forceinline__ void cpa_commit() { asm volatile("cp.async.commit_group;" ::: "memory"); }
__device__ __forceinline__ float gelu_tanh(float v) {
    float c = 0.7978845608028654f;
    float t = tanhf(c * (v + 0.044715f * v * v * v));
    return 0.5f * v * (1.0f + t);
}

// =============== prep: fp16 tokens + routing gates (fused) ===============
// 8 warps/block, warp per token; lane covers 32 floats as 8 float4s.
__global__ __launch_bounds__(256) void prep(const float* __restrict__ tokens,
                                            const float* __restrict__ pb) {
    int wid = threadIdx.x >> 5, lane = threadIdx.x & 31;
    int n = blockIdx.x * 8 + wid;
    const float* t = tokens + (size_t)n * DMODEL;
    __half* th = g_T + (size_t)n * DMODEL;
    float s0 = 0.f, s1 = 0.f, s2 = 0.f, s3 = 0.f;
#pragma unroll
    for (int u = 0; u < 8; u++) {
        int idx = u * 128 + lane * 4;
        float4 v = *(const float4*)(t + idx);
        *(__half2*)(th + idx)     = __floats2half2_rn(v.x, v.y);
        *(__half2*)(th + idx + 2) = __floats2half2_rn(v.z, v.w);
        float4 p0 = *(const float4*)(pb + idx);
        float4 p1 = *(const float4*)(pb + DMODEL + idx);
        float4 p2 = *(const float4*)(pb + 2 * DMODEL + idx);
        float4 p3 = *(const float4*)(pb + 3 * DMODEL + idx);
        s0 += v.x * p0.x + v.y * p0.y + v.z * p0.z + v.w * p0.w;
        s1 += v.x * p1.x + v.y * p1.y + v.z * p1.z + v.w * p1.w;
        s2 += v.x * p2.x + v.y * p2.y + v.z * p2.z + v.w * p2.w;
        s3 += v.x * p3.x + v.y * p3.y + v.z * p3.z + v.w * p3.w;
    }
#pragma unroll
    for (int o = 16; o > 0; o >>= 1) {
        s0 += __shfl_down_sync(0xffffffffu, s0, o);
        s1 += __shfl_down_sync(0xffffffffu, s1, o);
        s2 += __shfl_down_sync(0xffffffffu, s2, o);
        s3 += __shfl_down_sync(0xffffffffu, s3, o);
    }
    if (lane == 0) {
        float m = fmaxf(fmaxf(s0, s1), fmaxf(s2, s3));
        float e0 = expf(s0 - m), e1 = expf(s1 - m), e2 = expf(s2 - m), e3 = expf(s3 - m);
        float inv = 1.f / (e0 + e1 + e2 + e3);
        g_gates[n * KP + 0] = e0 * inv;
        g_gates[n * KP + 1] = e1 * inv;
        g_gates[n * KP + 2] = e2 * inv;
        g_gates[n * KP + 3] = e3 * inv;
    }
}

// =============== zero the output (red.global targets it) ===============
__global__ void zero_out(float* __restrict__ out) {
    size_t i = ((size_t)blockIdx.x * 256 + threadIdx.x) * 4;
    *(float4*)(out + i) = make_float4(0.f, 0.f, 0.f, 0.f);
}

// =============== weight expansion (fp16, K-major) ===============
// W1t[kp][x*64+y][a*32+b] = sum_r G1[kp,a,x,r]*G2[kp,r,b,y]
__global__ void build_w1t(const float* __restrict__ G1, const float* __restrict__ G2) {
    __shared__ float G2s[16 * 32 * 17];
    __shared__ float G1s[32 * 16];
    int tid = threadIdx.x;
    int x = blockIdx.x, y0 = blockIdx.y * 16, kp = blockIdx.z;
    for (int e = tid; e < 8192; e += 256) {
        int r = e >> 9, b = (e >> 4) & 31, yl = e & 15;
        G2s[(r * 32 + b) * 17 + yl] = G2[((size_t)(kp * 16 + r) * 32 + b) * 64 + y0 + yl];
    }
    for (int e = tid; e < 512; e += 256) {
        int a = e >> 4, r = e & 15;
        G1s[e] = G1[((size_t)(kp * 32 + a) * 64 + x) * 16 + r];
    }
    __syncthreads();
#pragma unroll
    for (int i = 0; i < 4; i++) {       // k in [0, DMODEL)
        int k = tid + 256 * i;          // a*32+b
        int a = k >> 5, b = k & 31;
        float acc[16];
#pragma unroll
        for (int y = 0; y < 16; y++) acc[y] = 0.f;
#pragma unroll
        for (int r = 0; r < 16; r++) {
            float g1 = G1s[a * 16 + r];
#pragma unroll
            for (int y = 0; y < 16; y++)
                acc[y] = fmaf(g1, G2s[(r * 32 + b) * 17 + y], acc[y]);
        }
#pragma unroll
        for (int y = 0; y < 16; y++)
            g_W1t[((size_t)kp * DFF + x * 64 + y0 + y) * DMODEL + k] = __float2half_rn(acc[y]);
    }
}

// W2t[kp][x*32+y][a*64+b] = (1+pw[kp][d]) * sum_r C1[kp,a,x,r]*C2[kp,r,b,y]
__global__ void build_w2t(const float* __restrict__ C1, const float* __restrict__ C2,
                          const float* __restrict__ pw) {
    __shared__ float C2s[16 * 64 * 9];
    __shared__ float C1s[64 * 16];
    int tid = threadIdx.x;
    int x = blockIdx.x, y0 = blockIdx.y * 8, kp = blockIdx.z;
    for (int e = tid; e < 8192; e += 256) {
        int r = e >> 9, b = (e >> 3) & 63, yl = e & 7;
        C2s[(r * 64 + b) * 9 + yl] = C2[((size_t)(kp * 16 + r) * 64 + b) * 32 + y0 + yl];
    }
    for (int e = tid; e < 1024; e += 256) {
        int a = e >> 4, r = e & 15;
        C1s[e] = C1[((size_t)(kp * 64 + a) * 32 + x) * 16 + r];
    }
    __syncthreads();
#pragma unroll
    for (int i = 0; i < 16; i++) {      // f in [0, DFF)
        int f = tid + 256 * i;          // a*64+b
        int a = f >> 6, b = f & 63;
        float acc[8];
#pragma unroll
        for (int y = 0; y < 8; y++) acc[y] = 0.f;
#pragma unroll
        for (int r = 0; r < 16; r++) {
            float c1 = C1s[a * 16 + r];
#pragma unroll
            for (int y = 0; y < 8; y++)
                acc[y] = fmaf(c1, C2s[(r * 64 + b) * 9 + y], acc[y]);
        }
#pragma unroll
        for (int y = 0; y < 8; y++) {
            int d = x * 32 + y0 + y;
            g_W2t[((size_t)kp * DMODEL + d) * DFF + f] =
                __float2half_rn(acc[y] * (1.f + pw[kp * DMODEL + d]));
        }
    }
}

// =============== fp16 mma.sync GEMM ===============
__device__ __forceinline__ void fill_tile(uint32_t sbase, int buf,
                                          const __half* __restrict__ A, int lda,
                                          const __half* __restrict__ B, int ldb,
                                          int m0, int n0, int k0, int tid) {
    uint32_t ab = sbase + buf * STAGE_B;
    uint32_t bb = ab + TILE_B;
#pragma unroll
    for (int u = 0; u < 4; u++) {
        int idx = tid + 256 * u;              // 0..1023
        int row = idx >> 3, seg = idx & 7;
        cpa16(ab + row * (ROWH * 2) + seg * 16, A + (size_t)(m0 + row) * lda + k0 + seg * 8);
        cpa16(bb + row * (ROWH * 2) + seg * 16, B + (size_t)(n0 + row) * ldb + k0 + seg * 8);
    }
}

// MODE 0: g_T @ W1t -> gate*gelu -> g_H (fp16)
// MODE 1: g_H @ W2t -> red.global.add into out (fp32)
template <int MODE>
__global__ __launch_bounds__(256, 2) void gemm_tc(float* __restrict__ out) {
    extern __shared__ char smb[];
    uint32_t sbase = smem_u32(smb);

    int tid = threadIdx.x;
    int wid = tid >> 5, lane = tid & 31;
    int g = lane >> 2, tig = lane & 3;
    int kp = blockIdx.z;
    int m0 = blockIdx.y * BM, n0 = blockIdx.x * BN;

    const int lda = (MODE == 0) ? DMODEL : DFF;
    const int ldb = (MODE == 0) ? DMODEL : DFF;
    const int Ktot = (MODE == 0) ? DMODEL : DFF;
    const __half* A = (MODE == 0) ? g_T : (g_H + (size_t)kp * NTOK * DFF);
    const __half* B = (MODE == 0) ? (g_W1t + (size_t)kp * DFF * DMODEL)
                                  : (g_W2t + (size_t)kp * DMODEL * DFF);

    const int rm = (wid >> 2) * 64;   // warp m offset (0,64)
    const int cn = (wid & 3) * 32;    // warp n offset (0..96)

    // precomputed per-lane ldmatrix row/col offsets (in halves)
    const uint32_t a_off = (uint32_t)((rm + (lane & 15)) * ROWH + (lane >> 4) * 8);
    const uint32_t b_off = (uint32_t)((cn + ((lane >> 4) & 1) * 8 + (lane & 7)) * ROWH
                                      + ((lane >> 3) & 1) * 8);

    float d[4][4][4];
#pragma unroll
    for (int i = 0; i < 4; i++)
#pragma unroll
        for (int j = 0; j < 4; j++)
#pragma unroll
            for (int q = 0; q < 4; q++) d[i][j][q] = 0.f;

    const int NK = Ktot / BK;
    fill_tile(sbase, 0, A, lda, B, ldb, m0, n0, 0, tid); cpa_commit();
    fill_tile(sbase, 1, A, lda, B, ldb, m0, n0, BK, tid); cpa_commit();

    for (int kt = 0; kt < NK; kt++) {
        asm volatile("cp.async.wait_group 1;" ::: "memory");
        __syncthreads();
        int buf = kt % 3;
        uint32_t abase = sbase + buf * STAGE_B;
        uint32_t bbase = abase + TILE_B;
#pragma unroll
        for (int ks = 0; ks < 4; ks++) {
            int klo = ks * 16;
            uint32_t a[4][4], b[4][2];
#pragma unroll
            for (int mb = 0; mb < 4; mb++) {
                uint32_t addr = abase + 2 * (a_off + (uint32_t)(mb * 16 * ROWH + klo));
                asm volatile("ldmatrix.sync.aligned.m8n8.x4.shared.b16 {%0,%1,%2,%3}, [%4];"
                             : "=r"(a[mb][0]), "=r"(a[mb][1]), "=r"(a[mb][2]), "=r"(a[mb][3])
                             : "r"(addr));
            }
#pragma unroll
            for (int pr = 0; pr < 2; pr++) {
                uint32_t addr = bbase + 2 * (b_off + (uint32_t)(pr * 16 * ROWH + klo));
                asm volatile("ldmatrix.sync.aligned.m8n8.x4.shared.b16 {%0,%1,%2,%3}, [%4];"
                             : "=r"(b[2 * pr][0]), "=r"(b[2 * pr][1]),
                               "=r"(b[2 * pr + 1][0]), "=r"(b[2 * pr + 1][1])
                             : "r"(addr));
            }
#pragma unroll
            for (int mb = 0; mb < 4; mb++)
#pragma unroll
                for (int nb = 0; nb < 4; nb++)
                    asm volatile(
                        "mma.sync.aligned.m16n8k16.row.col.f32.f16.f16.f32 "
                        "{%0,%1,%2,%3}, {%4,%5,%6,%7}, {%8,%9}, {%0,%1,%2,%3};"
                        : "+f"(d[mb][nb][0]), "+f"(d[mb][nb][1]),
                          "+f"(d[mb][nb][2]), "+f"(d[mb][nb][3])
                        : "r"(a[mb][0]), "r"(a[mb][1]), "r"(a[mb][2]), "r"(a[mb][3]),
                          "r"(b[nb][0]), "r"(b[nb][1]));
        }
        if (kt + 2 < NK)
            fill_tile(sbase, (kt + 2) % 3, A, lda, B, ldb, m0, n0, (kt + 2) * BK, tid);
        cpa_commit();
    }

    __syncthreads();  // mainloop done; smem reusable

    if (MODE == 0) {
        // gate * gelu -> fp16 g_H, coalesced via smem transpose (16r x 32c per mb per warp)
        __half* C = g_H + (size_t)kp * NTOK * DFF;
        __half* ws = (__half*)smb + wid * (16 * ROWH);
#pragma unroll
        for (int mb = 0; mb < 4; mb++) {
            int grow = m0 + rm + mb * 16;
            float gate_lo = g_gates[(size_t)(grow + g) * KP + kp];
            float gate_hi = g_gates[(size_t)(grow + g + 8) * KP + kp];
#pragma unroll
            for (int nb = 0; nb < 4; nb++) {
                int c = nb * 8 + 2 * tig;
                float v0 = gate_lo * gelu_tanh(d[mb][nb][0]);
                float v1 = gate_lo * gelu_tanh(d[mb][nb][1]);
                float v2 = gate_hi * gelu_tanh(d[mb][nb][2]);
                float v3 = gate_hi * gelu_tanh(d[mb][nb][3]);
                *(__half2*)(ws + g * ROWH + c) = __floats2half2_rn(v0, v1);
                *(__half2*)(ws + (g + 8) * ROWH + c) = __floats2half2_rn(v2, v3);
            }
            __syncwarp();
            int row = lane >> 1, part = lane & 1;
            const uint4* src = (const uint4*)(ws + row * ROWH + part * 16);
            __half* dst = C + (size_t)(grow + row) * DFF + n0 + cn + part * 16;
#pragma unroll
            for (int q = 0; q < 2; q++)
                *(uint4*)(dst + q * 8) = src[q];
            __syncwarp();
        }
    } else {
        // accumulate across the 4 paths directly into out via red.global.add
#pragma unroll
        for (int mb = 0; mb < 4; mb++) {
            int grow = m0 + rm + mb * 16;
#pragma unroll
            for (int nb = 0; nb < 4; nb++) {
                int col = n0 + cn + nb * 8 + 2 * tig;
                float* p0 = out + (size_t)(grow + g) * DMODEL + col;
                float* p1 = out + (size_t)(grow + g + 8) * DMODEL + col;
                asm volatile("red.global.add.f32 [%0], %1;" :: "l"(p0), "f"(d[mb][nb][0]) : "memory");
                asm volatile("red.global.add.f32 [%0], %1;" :: "l"(p0 + 1), "f"(d[mb][nb][1]) : "memory");
                asm volatile("red.global.add.f32 [%0], %1;" :: "l"(p1), "f"(d[mb][nb][2]) : "memory");
                asm volatile("red.global.add.f32 [%0], %1;" :: "l"(p1 + 1), "f"(d[mb][nb][3]) : "memory");
            }
        }
    }
}

// ===========================================================================
extern "C" void kernel_launch(void* const* d_in, const int* in_sizes, int n_in,
                              void* d_out, int out_size) {
    const float* tokens = (const float*)d_in[0];
    const float* G1 = (const float*)d_in[1];  // [4,32,64,16]
    const float* G2 = (const float*)d_in[2];  // [4,16,32,64]
    const float* C1 = (const float*)d_in[3];  // [4,64,32,16]
    const float* C2 = (const float*)d_in[4];  // [4,16,64,32]
    const float* pb = (const float*)d_in[5];  // [4,1024]
    const float* pw = (const float*)d_in[6];  // [4,1024]
    float* out = (float*)d_out;

    cudaFuncSetAttribute(gemm_tc<0>, cudaFuncAttributeMaxDynamicSharedMemorySize, SMEM_DYN);
    cudaFuncSetAttribute(gemm_tc<1>, cudaFuncAttributeMaxDynamicSharedMemorySize, SMEM_DYN);

    prep<<<NTOK / 8, 256>>>(tokens, pb);
    build_w1t<<<dim3(64, 4, KP), 256>>>(G1, G2);
    build_w2t<<<dim3(32, 4, KP), 256>>>(C1, C2, pw);
    zero_out<<<(NTOK * DMODEL / 4) / 256, 256>>>(out);
    gemm_tc<0><<<dim3(DFF / BN, NTOK / BM, KP), 256, SMEM_DYN>>>(out);
    gemm_tc<1><<<dim3(DMODEL / BN, NTOK / BM, KP), 256, SMEM_DYN>>>(out);
}